// round 2
// baseline (speedup 1.0000x reference)
#include <cuda_runtime.h>
#include <cuda_bf16.h>
#include <cstdint>

// ---------------- problem constants ----------------
#define D_MODEL   256
#define N_HEADS   8
#define HEAD_DIM  32
#define N_LEVELS  4
#define N_POINTS  4
#define D_FFN     1024
#define HW        128
#define LQ        (HW * HW)            // 16384
#define LIN       (N_LEVELS * LQ)      // 65536
#define BATCH     2
#define ROWS_Q    (BATCH * LQ)         // 32768
#define ROWS_V    (BATCH * LIN)        // 131072

// ---------------- scratch (device globals; allocation-free rule) ----------
__device__ float sc_value[ROWS_V * D_MODEL];   // 134 MB
__device__ float sc_q    [ROWS_Q * D_MODEL];   // 33.5 MB
__device__ float sc_off  [ROWS_Q * D_MODEL];   // 33.5 MB (8*4*4*2 = 256 per row)
__device__ float sc_attn [ROWS_Q * 128];       // 16.8 MB
__device__ float sc_samp [ROWS_Q * D_MODEL];   // 33.5 MB
__device__ float sc_src2 [ROWS_Q * D_MODEL];   // 33.5 MB
__device__ float sc_src  [ROWS_Q * D_MODEL];   // 33.5 MB
__device__ float sc_ffn  [ROWS_Q * D_FFN];     // 134 MB
__device__ float sc_ffn2 [ROWS_Q * D_MODEL];   // 33.5 MB

// ---------------- fp32 tiled GEMM: C = (A [+A2]) @ B + bias [, relu] ------
// A: MxK row-major, B: KxN row-major, C: MxN row-major.
// BM=BN=64, BK=16, 256 threads, 4x4 micro-tile. M%64==0, N%64==0, K%16==0.
template <bool FUSE_ADD, bool RELU>
__global__ __launch_bounds__(256)
void sgemm_kernel(const float* __restrict__ A, const float* __restrict__ A2,
                  const float* __restrict__ B, const float* __restrict__ bias,
                  float* __restrict__ C, int M, int N, int K)
{
    __shared__ float As[16][64];
    __shared__ float Bs[16][64];

    const int bm = blockIdx.y * 64;
    const int bn = blockIdx.x * 64;
    const int tid = threadIdx.x;
    const int tx = tid & 15;   // N direction (x4)
    const int ty = tid >> 4;   // M direction (x4)

    float acc[4][4] = {};

    // load indices
    const int la_m  = tid >> 2;          // 0..63
    const int la_k  = (tid & 3) * 4;     // 0,4,8,12
    const int lb_k  = tid >> 4;          // 0..15
    const int lb_n  = (tid & 15) * 4;    // 0..60

    for (int k0 = 0; k0 < K; k0 += 16) {
        // A tile (64x16) -> transposed into As[k][m]
        {
            const float* ap = A + (size_t)(bm + la_m) * K + k0 + la_k;
            float4 av = *(const float4*)ap;
            if (FUSE_ADD) {
                const float4 av2 = *(const float4*)(A2 + (size_t)(bm + la_m) * K + k0 + la_k);
                av.x += av2.x; av.y += av2.y; av.z += av2.z; av.w += av2.w;
            }
            As[la_k + 0][la_m] = av.x;
            As[la_k + 1][la_m] = av.y;
            As[la_k + 2][la_m] = av.z;
            As[la_k + 3][la_m] = av.w;
        }
        // B tile (16x64)
        {
            const float4 bv = *(const float4*)(B + (size_t)(k0 + lb_k) * N + bn + lb_n);
            *(float4*)&Bs[lb_k][lb_n] = bv;
        }
        __syncthreads();

        #pragma unroll
        for (int k = 0; k < 16; ++k) {
            const float4 a4 = *(const float4*)&As[k][ty * 4];
            const float4 b4 = *(const float4*)&Bs[k][tx * 4];
            const float a[4] = {a4.x, a4.y, a4.z, a4.w};
            const float b[4] = {b4.x, b4.y, b4.z, b4.w};
            #pragma unroll
            for (int i = 0; i < 4; ++i)
                #pragma unroll
                for (int j = 0; j < 4; ++j)
                    acc[i][j] = fmaf(a[i], b[j], acc[i][j]);
        }
        __syncthreads();
    }

    const int nbase = bn + tx * 4;
    const float4 bv = *(const float4*)&bias[nbase];
    #pragma unroll
    for (int i = 0; i < 4; ++i) {
        const int m = bm + ty * 4 + i;
        float4 v;
        v.x = acc[i][0] + bv.x;
        v.y = acc[i][1] + bv.y;
        v.z = acc[i][2] + bv.z;
        v.w = acc[i][3] + bv.w;
        if (RELU) {
            v.x = fmaxf(v.x, 0.f); v.y = fmaxf(v.y, 0.f);
            v.z = fmaxf(v.z, 0.f); v.w = fmaxf(v.w, 0.f);
        }
        *(float4*)&C[(size_t)m * N + nbase] = v;
    }
}

// ---------------- q = cur_src + pos[:, -1] --------------------------------
__global__ __launch_bounds__(256)
void add_q_kernel(const float* __restrict__ cur, const float* __restrict__ pos,
                  float* __restrict__ q)
{
    const size_t i = (size_t)blockIdx.x * blockDim.x + threadIdx.x; // < ROWS_Q*D/4
    const size_t per_batch = (size_t)LQ * D_MODEL / 4;
    const size_t n = i / per_batch;
    const size_t r = i - n * per_batch;
    const float4* c4 = (const float4*)cur;
    const float4* p4 = (const float4*)pos;
    float4 a = c4[i];
    float4 b = p4[n * 4 * per_batch + 3 * per_batch + r];
    a.x += b.x; a.y += b.y; a.z += b.z; a.w += b.w;
    ((float4*)q)[i] = a;
}

// ---------------- fused softmax + deformable bilinear sampling ------------
// One warp per (n, q, h). lane = head-dim channel (coalesced 128B gathers).
__global__ __launch_bounds__(256)
void sample_kernel(const float* __restrict__ off, const float* __restrict__ attn,
                   const float* __restrict__ ref, const float* __restrict__ value,
                   float* __restrict__ out)
{
    const int gw   = blockIdx.x * 8 + (threadIdx.x >> 5);
    const int lane = threadIdx.x & 31;
    const int h = gw & 7;
    const int q = (gw >> 3) & (LQ - 1);
    const int n = gw >> 17;

    const size_t row = (size_t)n * LQ + q;
    const float* ap = attn + row * 128 + h * 16;

    // softmax over 16 (redundant per lane; L1 broadcast)
    float logits[16];
    float mx = -1e30f;
    #pragma unroll
    for (int i = 0; i < 16; ++i) { logits[i] = ap[i]; mx = fmaxf(mx, logits[i]); }
    float ssum = 0.f;
    #pragma unroll
    for (int i = 0; i < 16; ++i) { logits[i] = __expf(logits[i] - mx); ssum += logits[i]; }
    const float inv = 1.f / ssum;

    const float* op = off + row * 256 + h * 32;
    const float* rp = ref + row * 8;           // (l, 2)
    const float* vb = value + (size_t)n * LIN * 256 + h * 32 + lane;

    float acc = 0.f;
    #pragma unroll
    for (int l = 0; l < N_LEVELS; ++l) {
        const float rx = rp[l * 2 + 0];
        const float ry = rp[l * 2 + 1];
        const int start = l * LQ;
        #pragma unroll
        for (int p = 0; p < N_POINTS; ++p) {
            // loc*W - 0.5 with W=H=128 and normalizer 128: x = rx*128 + ox - 0.5
            const float x = fmaf(rx, 128.f, op[l * 8 + p * 2 + 0] - 0.5f);
            const float y = fmaf(ry, 128.f, op[l * 8 + p * 2 + 1] - 0.5f);
            const float x0f = floorf(x), y0f = floorf(y);
            const float wx = x - x0f, wy = y - y0f;
            const int x0 = (int)x0f, y0 = (int)y0f;
            const float aw = logits[l * 4 + p] * inv;

            const bool vx0 = (x0 >= 0) & (x0 < HW);
            const bool vx1 = (x0 + 1 >= 0) & (x0 + 1 < HW);
            const bool vy0 = (y0 >= 0) & (y0 < HW);
            const bool vy1 = (y0 + 1 >= 0) & (y0 + 1 < HW);

            if (vy0) {
                const size_t base = (size_t)(start + y0 * HW) * 256;
                if (vx0) acc = fmaf(vb[base + (size_t)x0 * 256],
                                    (1.f - wx) * (1.f - wy) * aw, acc);
                if (vx1) acc = fmaf(vb[base + (size_t)(x0 + 1) * 256],
                                    wx * (1.f - wy) * aw, acc);
            }
            if (vy1) {
                const size_t base = (size_t)(start + (y0 + 1) * HW) * 256;
                if (vx0) acc = fmaf(vb[base + (size_t)x0 * 256],
                                    (1.f - wx) * wy * aw, acc);
                if (vx1) acc = fmaf(vb[base + (size_t)(x0 + 1) * 256],
                                    wx * wy * aw, acc);
            }
        }
    }
    out[row * 256 + h * 32 + lane] = acc;
}

// ---------------- residual add + layernorm (D=256, one block per row) -----
__global__ __launch_bounds__(256)
void add_ln_kernel(const float* __restrict__ a, const float* __restrict__ b,
                   const float* __restrict__ gamma, const float* __restrict__ beta,
                   float* __restrict__ out)
{
    const int row = blockIdx.x;
    const int t = threadIdx.x;
    const size_t idx = (size_t)row * 256 + t;
    const float v = a[idx] + b[idx];

    __shared__ float red[8];
    float s = v;
    #pragma unroll
    for (int o = 16; o; o >>= 1) s += __shfl_xor_sync(0xffffffffu, s, o);
    if ((t & 31) == 0) red[t >> 5] = s;
    __syncthreads();
    float mean = 0.f;
    #pragma unroll
    for (int i = 0; i < 8; ++i) mean += red[i];
    mean *= (1.f / 256.f);
    __syncthreads();

    const float d = v - mean;
    float s2 = d * d;
    #pragma unroll
    for (int o = 16; o; o >>= 1) s2 += __shfl_xor_sync(0xffffffffu, s2, o);
    if ((t & 31) == 0) red[t >> 5] = s2;
    __syncthreads();
    float var = 0.f;
    #pragma unroll
    for (int i = 0; i < 8; ++i) var += red[i];
    var *= (1.f / 256.f);

    out[idx] = d * rsqrtf(var + 1e-5f) * gamma[t] + beta[t];
}

// ---------------- launch ---------------------------------------------------
extern "C" void kernel_launch(void* const* d_in, const int* in_sizes, int n_in,
                              void* d_out, int out_size)
{
    (void)in_sizes; (void)n_in; (void)out_size;
    const float* cur_src = (const float*)d_in[0];
    const float* src_all = (const float*)d_in[1];
    const float* pos     = (const float*)d_in[2];
    const float* refpts  = (const float*)d_in[3];
    // d_in[4] spatial_shape, d_in[5] level_start_index: static, unused
    const float* W_off   = (const float*)d_in[6];
    const float* b_off   = (const float*)d_in[7];
    const float* W_attn  = (const float*)d_in[8];
    const float* b_attn  = (const float*)d_in[9];
    const float* W_val   = (const float*)d_in[10];
    const float* b_val   = (const float*)d_in[11];
    const float* W_out   = (const float*)d_in[12];
    const float* b_out   = (const float*)d_in[13];
    const float* gamma1  = (const float*)d_in[14];
    const float* beta1   = (const float*)d_in[15];
    const float* W1      = (const float*)d_in[16];
    const float* b1      = (const float*)d_in[17];
    const float* W2      = (const float*)d_in[18];
    const float* b2      = (const float*)d_in[19];
    const float* gamma2  = (const float*)d_in[20];
    const float* beta2   = (const float*)d_in[21];
    float* out = (float*)d_out;

    float *g_value, *g_q, *g_off, *g_attn, *g_samp, *g_src2, *g_src, *g_ffn, *g_ffn2;
    cudaGetSymbolAddress((void**)&g_value, sc_value);
    cudaGetSymbolAddress((void**)&g_q,     sc_q);
    cudaGetSymbolAddress((void**)&g_off,   sc_off);
    cudaGetSymbolAddress((void**)&g_attn,  sc_attn);
    cudaGetSymbolAddress((void**)&g_samp,  sc_samp);
    cudaGetSymbolAddress((void**)&g_src2,  sc_src2);
    cudaGetSymbolAddress((void**)&g_src,   sc_src);
    cudaGetSymbolAddress((void**)&g_ffn,   sc_ffn);
    cudaGetSymbolAddress((void**)&g_ffn2,  sc_ffn2);

    // 1. q = cur_src + pos[:, -1]
    add_q_kernel<<<(ROWS_Q * D_MODEL / 4) / 256, 256>>>(cur_src, pos, g_q);

    // 2. value = (src_all + pos_flat) @ W_val + b_val   (M=131072, N=256, K=256)
    sgemm_kernel<true, false><<<dim3(D_MODEL / 64, ROWS_V / 64), 256>>>(
        src_all, pos, W_val, b_val, g_value, ROWS_V, D_MODEL, D_MODEL);

    // 3. off = q @ W_off + b_off                        (M=32768, N=256, K=256)
    sgemm_kernel<false, false><<<dim3(256 / 64, ROWS_Q / 64), 256>>>(
        g_q, nullptr, W_off, b_off, g_off, ROWS_Q, 256, D_MODEL);

    // 4. attn_logits = q @ W_attn + b_attn              (M=32768, N=128, K=256)
    sgemm_kernel<false, false><<<dim3(128 / 64, ROWS_Q / 64), 256>>>(
        g_q, nullptr, W_attn, b_attn, g_attn, ROWS_Q, 128, D_MODEL);

    // 5. fused softmax + deformable bilinear sampling
    sample_kernel<<<(BATCH * LQ * N_HEADS) / 8, 256>>>(
        g_off, g_attn, refpts, g_value, g_samp);

    // 6. src2 = samp @ W_out + b_out                    (M=32768, N=256, K=256)
    sgemm_kernel<false, false><<<dim3(D_MODEL / 64, ROWS_Q / 64), 256>>>(
        g_samp, nullptr, W_out, b_out, g_src2, ROWS_Q, D_MODEL, D_MODEL);

    // 7. src = LN(cur_src + src2)
    add_ln_kernel<<<ROWS_Q, 256>>>(cur_src, g_src2, gamma1, beta1, g_src);

    // 8. ffn_h = relu(src @ W1 + b1)                    (M=32768, N=1024, K=256)
    sgemm_kernel<false, true><<<dim3(D_FFN / 64, ROWS_Q / 64), 256>>>(
        g_src, nullptr, W1, b1, g_ffn, ROWS_Q, D_FFN, D_MODEL);

    // 9. ffn2 = ffn_h @ W2 + b2                         (M=32768, N=256, K=1024)
    sgemm_kernel<false, false><<<dim3(D_MODEL / 64, ROWS_Q / 64), 256>>>(
        g_ffn, nullptr, W2, b2, g_ffn2, ROWS_Q, D_MODEL, D_FFN);

    // 10. out = LN(src + ffn2)
    add_ln_kernel<<<ROWS_Q, 256>>>(g_src, g_ffn2, gamma2, beta2, out);
}

// round 3
// speedup vs baseline: 1.9513x; 1.9513x over previous
#include <cuda_runtime.h>
#include <cuda_bf16.h>
#include <cstdint>

// ---------------- problem constants ----------------
#define D_MODEL   256
#define N_HEADS   8
#define HEAD_DIM  32
#define N_LEVELS  4
#define N_POINTS  4
#define D_FFN     1024
#define HW        128
#define LQ        (HW * HW)            // 16384
#define LIN       (N_LEVELS * LQ)      // 65536
#define BATCH     2
#define ROWS_Q    (BATCH * LQ)         // 32768
#define ROWS_V    (BATCH * LIN)        // 131072

// ---------------- scratch (device globals; allocation-free rule) ----------
__device__ float sc_value[ROWS_V * D_MODEL];   // 134 MB
__device__ float sc_q    [ROWS_Q * D_MODEL];   // 33.5 MB
__device__ float sc_off  [ROWS_Q * D_MODEL];   // 33.5 MB
__device__ float sc_attn [ROWS_Q * 128];       // 16.8 MB
__device__ float sc_samp [ROWS_Q * D_MODEL];   // 33.5 MB
__device__ float sc_src2 [ROWS_Q * D_MODEL];   // 33.5 MB
__device__ float sc_src  [ROWS_Q * D_MODEL];   // 33.5 MB
__device__ float sc_ffn  [ROWS_Q * D_FFN];     // 134 MB
__device__ float sc_ffn2 [ROWS_Q * D_MODEL];   // 33.5 MB

// ---------------- helpers --------------------------------------------------
__device__ __forceinline__ uint32_t f2tf32(float f) {
    uint32_t u;
    asm("cvt.rna.tf32.f32 %0, %1;" : "=r"(u) : "f"(f));
    return u;
}

__device__ __forceinline__ void mma_tf32(float c[4], const uint32_t a[4],
                                         const uint32_t b[2]) {
    asm volatile(
        "mma.sync.aligned.m16n8k8.row.col.f32.tf32.tf32.f32 "
        "{%0,%1,%2,%3}, {%4,%5,%6,%7}, {%8,%9}, {%0,%1,%2,%3};"
        : "+f"(c[0]), "+f"(c[1]), "+f"(c[2]), "+f"(c[3])
        : "r"(a[0]), "r"(a[1]), "r"(a[2]), "r"(a[3]), "r"(b[0]), "r"(b[1]));
}

// ---------------- TF32 tensor-core GEMM -----------------------------------
// C = (A [+A2]) @ B + bias [, relu].  A: MxK rm, B: KxN rm, C: MxN rm.
// BM=BN=128, BK=16, 256 threads (8 warps, 2x4), warp tile 64x32.
// Requires M%128==0, N%128==0, K%16==0.
#define BK 16
#define A_PAD 20    // row stride of As (floats): conflict-free frag loads
#define B_PAD 136   // row stride of Bs (floats): conflict-free frag loads

template <bool FUSE_ADD, bool RELU>
__global__ __launch_bounds__(256)
void tgemm_kernel(const float* __restrict__ A, const float* __restrict__ A2,
                  const float* __restrict__ B, const float* __restrict__ bias,
                  float* __restrict__ C, int M, int N, int K)
{
    __shared__ uint32_t As[2][128 * A_PAD];   // [m][k], row stride A_PAD
    __shared__ uint32_t Bs[2][BK * B_PAD];    // [k][n], row stride B_PAD

    const int tid  = threadIdx.x;
    const int wid  = tid >> 5;
    const int lane = tid & 31;
    const int g    = lane >> 2;     // group id (rows / cols of fragments)
    const int t    = lane & 3;      // thread-in-group

    const int bm = blockIdx.y * 128;
    const int bn = blockIdx.x * 128;
    const int wm = (wid & 1) * 64;  // warp M offset within block
    const int wn = (wid >> 1) * 32; // warp N offset within block

    // global-load mapping
    const int la_m = tid >> 1;            // 0..127
    const int la_k = (tid & 1) * 8;       // 0 or 8
    const int lb_k = tid >> 4;            // 0..15
    const int lb_n = (tid & 15) * 8;      // 0..120

    const float* a_ptr  = A  + (size_t)(bm + la_m) * K + la_k;
    const float* a2_ptr = FUSE_ADD ? (A2 + (size_t)(bm + la_m) * K + la_k) : nullptr;
    const float* b_ptr  = B  + (size_t)lb_k * N + bn + lb_n;

    float acc[4][4][4] = {};  // [mt][nt][reg]

    // ---- load tile 0 ----
    {
        float4 av0 = *(const float4*)(a_ptr);
        float4 av1 = *(const float4*)(a_ptr + 4);
        if (FUSE_ADD) {
            const float4 w0 = *(const float4*)(a2_ptr);
            const float4 w1 = *(const float4*)(a2_ptr + 4);
            av0.x += w0.x; av0.y += w0.y; av0.z += w0.z; av0.w += w0.w;
            av1.x += w1.x; av1.y += w1.y; av1.z += w1.z; av1.w += w1.w;
        }
        uint32_t* as = &As[0][la_m * A_PAD + la_k];
        as[0] = f2tf32(av0.x); as[1] = f2tf32(av0.y);
        as[2] = f2tf32(av0.z); as[3] = f2tf32(av0.w);
        as[4] = f2tf32(av1.x); as[5] = f2tf32(av1.y);
        as[6] = f2tf32(av1.z); as[7] = f2tf32(av1.w);

        const float4 bv0 = *(const float4*)(b_ptr);
        const float4 bv1 = *(const float4*)(b_ptr + 4);
        uint32_t* bs = &Bs[0][lb_k * B_PAD + lb_n];
        bs[0] = f2tf32(bv0.x); bs[1] = f2tf32(bv0.y);
        bs[2] = f2tf32(bv0.z); bs[3] = f2tf32(bv0.w);
        bs[4] = f2tf32(bv1.x); bs[5] = f2tf32(bv1.y);
        bs[6] = f2tf32(bv1.z); bs[7] = f2tf32(bv1.w);
    }
    __syncthreads();

    int buf = 0;
    for (int k0 = 0; k0 < K; k0 += BK) {
        const bool more = (k0 + BK) < K;
        float4 av0, av1, bv0, bv1;
        if (more) {
            av0 = *(const float4*)(a_ptr + (k0 + BK));
            av1 = *(const float4*)(a_ptr + (k0 + BK) + 4);
            if (FUSE_ADD) {
                const float4 w0 = *(const float4*)(a2_ptr + (k0 + BK));
                const float4 w1 = *(const float4*)(a2_ptr + (k0 + BK) + 4);
                av0.x += w0.x; av0.y += w0.y; av0.z += w0.z; av0.w += w0.w;
                av1.x += w1.x; av1.y += w1.y; av1.z += w1.z; av1.w += w1.w;
            }
            bv0 = *(const float4*)(b_ptr + (size_t)(k0 + BK) * N);
            bv1 = *(const float4*)(b_ptr + (size_t)(k0 + BK) * N + 4);
        }

        // ---- compute on smem[buf] ----
        #pragma unroll
        for (int ks = 0; ks < BK; ks += 8) {
            uint32_t af[4][4];
            #pragma unroll
            for (int mt = 0; mt < 4; ++mt) {
                const int m = wm + mt * 16 + g;
                const uint32_t* p = &As[buf][m * A_PAD + ks + t];
                af[mt][0] = p[0];
                af[mt][1] = p[8 * A_PAD];
                af[mt][2] = p[4];
                af[mt][3] = p[8 * A_PAD + 4];
            }
            uint32_t bf[4][2];
            #pragma unroll
            for (int nt = 0; nt < 4; ++nt) {
                const int n = wn + nt * 8 + g;
                const uint32_t* p = &Bs[buf][(ks + t) * B_PAD + n];
                bf[nt][0] = p[0];
                bf[nt][1] = p[4 * B_PAD];
            }
            #pragma unroll
            for (int mt = 0; mt < 4; ++mt)
                #pragma unroll
                for (int nt = 0; nt < 4; ++nt)
                    mma_tf32(acc[mt][nt], af[mt], bf[nt]);
        }

        if (more) {
            uint32_t* as = &As[buf ^ 1][la_m * A_PAD + la_k];
            as[0] = f2tf32(av0.x); as[1] = f2tf32(av0.y);
            as[2] = f2tf32(av0.z); as[3] = f2tf32(av0.w);
            as[4] = f2tf32(av1.x); as[5] = f2tf32(av1.y);
            as[6] = f2tf32(av1.z); as[7] = f2tf32(av1.w);
            uint32_t* bs = &Bs[buf ^ 1][lb_k * B_PAD + lb_n];
            bs[0] = f2tf32(bv0.x); bs[1] = f2tf32(bv0.y);
            bs[2] = f2tf32(bv0.z); bs[3] = f2tf32(bv0.w);
            bs[4] = f2tf32(bv1.x); bs[5] = f2tf32(bv1.y);
            bs[6] = f2tf32(bv1.z); bs[7] = f2tf32(bv1.w);
            __syncthreads();
            buf ^= 1;
        }
    }

    // ---- epilogue: bias (+relu), float2 stores ----
    #pragma unroll
    for (int nt = 0; nt < 4; ++nt) {
        const int n = bn + wn + nt * 8 + t * 2;
        const float bx = bias[n], by = bias[n + 1];
        #pragma unroll
        for (int mt = 0; mt < 4; ++mt) {
            const int m = bm + wm + mt * 16 + g;
            float2 v0 = { acc[mt][nt][0] + bx, acc[mt][nt][1] + by };
            float2 v1 = { acc[mt][nt][2] + bx, acc[mt][nt][3] + by };
            if (RELU) {
                v0.x = fmaxf(v0.x, 0.f); v0.y = fmaxf(v0.y, 0.f);
                v1.x = fmaxf(v1.x, 0.f); v1.y = fmaxf(v1.y, 0.f);
            }
            *(float2*)&C[(size_t)m * N + n]       = v0;
            *(float2*)&C[(size_t)(m + 8) * N + n] = v1;
        }
    }
}

// ---------------- q = cur_src + pos[:, -1] --------------------------------
__global__ __launch_bounds__(256)
void add_q_kernel(const float* __restrict__ cur, const float* __restrict__ pos,
                  float* __restrict__ q)
{
    const size_t i = (size_t)blockIdx.x * blockDim.x + threadIdx.x;
    const size_t per_batch = (size_t)LQ * D_MODEL / 4;
    const size_t n = i / per_batch;
    const size_t r = i - n * per_batch;
    const float4* c4 = (const float4*)cur;
    const float4* p4 = (const float4*)pos;
    float4 a = c4[i];
    float4 b = p4[n * 4 * per_batch + 3 * per_batch + r];
    a.x += b.x; a.y += b.y; a.z += b.z; a.w += b.w;
    ((float4*)q)[i] = a;
}

// ---------------- fused softmax + deformable bilinear sampling ------------
__global__ __launch_bounds__(256)
void sample_kernel(const float* __restrict__ off, const float* __restrict__ attn,
                   const float* __restrict__ ref, const float* __restrict__ value,
                   float* __restrict__ out)
{
    const int gw   = blockIdx.x * 8 + (threadIdx.x >> 5);
    const int lane = threadIdx.x & 31;
    const int h = gw & 7;
    const int q = (gw >> 3) & (LQ - 1);
    const int n = gw >> 17;

    const size_t row = (size_t)n * LQ + q;
    const float* ap = attn + row * 128 + h * 16;

    float logits[16];
    float mx = -1e30f;
    #pragma unroll
    for (int i = 0; i < 16; ++i) { logits[i] = ap[i]; mx = fmaxf(mx, logits[i]); }
    float ssum = 0.f;
    #pragma unroll
    for (int i = 0; i < 16; ++i) { logits[i] = __expf(logits[i] - mx); ssum += logits[i]; }
    const float inv = 1.f / ssum;

    const float* op = off + row * 256 + h * 32;
    const float* rp = ref + row * 8;
    const float* vb = value + (size_t)n * LIN * 256 + h * 32 + lane;

    float acc = 0.f;
    #pragma unroll
    for (int l = 0; l < N_LEVELS; ++l) {
        const float rx = rp[l * 2 + 0];
        const float ry = rp[l * 2 + 1];
        const int start = l * LQ;
        #pragma unroll
        for (int p = 0; p < N_POINTS; ++p) {
            const float x = fmaf(rx, 128.f, op[l * 8 + p * 2 + 0] - 0.5f);
            const float y = fmaf(ry, 128.f, op[l * 8 + p * 2 + 1] - 0.5f);
            const float x0f = floorf(x), y0f = floorf(y);
            const float wx = x - x0f, wy = y - y0f;
            const int x0 = (int)x0f, y0 = (int)y0f;
            const float aw = logits[l * 4 + p] * inv;

            const bool vx0 = (x0 >= 0) & (x0 < HW);
            const bool vx1 = (x0 + 1 >= 0) & (x0 + 1 < HW);
            const bool vy0 = (y0 >= 0) & (y0 < HW);
            const bool vy1 = (y0 + 1 >= 0) & (y0 + 1 < HW);

            if (vy0) {
                const size_t base = (size_t)(start + y0 * HW) * 256;
                if (vx0) acc = fmaf(vb[base + (size_t)x0 * 256],
                                    (1.f - wx) * (1.f - wy) * aw, acc);
                if (vx1) acc = fmaf(vb[base + (size_t)(x0 + 1) * 256],
                                    wx * (1.f - wy) * aw, acc);
            }
            if (vy1) {
                const size_t base = (size_t)(start + (y0 + 1) * HW) * 256;
                if (vx0) acc = fmaf(vb[base + (size_t)x0 * 256],
                                    (1.f - wx) * wy * aw, acc);
                if (vx1) acc = fmaf(vb[base + (size_t)(x0 + 1) * 256],
                                    wx * wy * aw, acc);
            }
        }
    }
    out[row * 256 + h * 32 + lane] = acc;
}

// ---------------- residual add + layernorm --------------------------------
__global__ __launch_bounds__(256)
void add_ln_kernel(const float* __restrict__ a, const float* __restrict__ b,
                   const float* __restrict__ gamma, const float* __restrict__ beta,
                   float* __restrict__ out)
{
    const int row = blockIdx.x;
    const int t = threadIdx.x;
    const size_t idx = (size_t)row * 256 + t;
    const float v = a[idx] + b[idx];

    __shared__ float red[8];
    float s = v;
    #pragma unroll
    for (int o = 16; o; o >>= 1) s += __shfl_xor_sync(0xffffffffu, s, o);
    if ((t & 31) == 0) red[t >> 5] = s;
    __syncthreads();
    float mean = 0.f;
    #pragma unroll
    for (int i = 0; i < 8; ++i) mean += red[i];
    mean *= (1.f / 256.f);
    __syncthreads();

    const float d = v - mean;
    float s2 = d * d;
    #pragma unroll
    for (int o = 16; o; o >>= 1) s2 += __shfl_xor_sync(0xffffffffu, s2, o);
    if ((t & 31) == 0) red[t >> 5] = s2;
    __syncthreads();
    float var = 0.f;
    #pragma unroll
    for (int i = 0; i < 8; ++i) var += red[i];
    var *= (1.f / 256.f);

    out[idx] = d * rsqrtf(var + 1e-5f) * gamma[t] + beta[t];
}

// ---------------- launch ---------------------------------------------------
extern "C" void kernel_launch(void* const* d_in, const int* in_sizes, int n_in,
                              void* d_out, int out_size)
{
    (void)in_sizes; (void)n_in; (void)out_size;
    const float* cur_src = (const float*)d_in[0];
    const float* src_all = (const float*)d_in[1];
    const float* pos     = (const float*)d_in[2];
    const float* refpts  = (const float*)d_in[3];
    const float* W_off   = (const float*)d_in[6];
    const float* b_off   = (const float*)d_in[7];
    const float* W_attn  = (const float*)d_in[8];
    const float* b_attn  = (const float*)d_in[9];
    const float* W_val   = (const float*)d_in[10];
    const float* b_val   = (const float*)d_in[11];
    const float* W_out   = (const float*)d_in[12];
    const float* b_out   = (const float*)d_in[13];
    const float* gamma1  = (const float*)d_in[14];
    const float* beta1   = (const float*)d_in[15];
    const float* W1      = (const float*)d_in[16];
    const float* b1      = (const float*)d_in[17];
    const float* W2      = (const float*)d_in[18];
    const float* b2      = (const float*)d_in[19];
    const float* gamma2  = (const float*)d_in[20];
    const float* beta2   = (const float*)d_in[21];
    float* out = (float*)d_out;

    float *g_value, *g_q, *g_off, *g_attn, *g_samp, *g_src2, *g_src, *g_ffn, *g_ffn2;
    cudaGetSymbolAddress((void**)&g_value, sc_value);
    cudaGetSymbolAddress((void**)&g_q,     sc_q);
    cudaGetSymbolAddress((void**)&g_off,   sc_off);
    cudaGetSymbolAddress((void**)&g_attn,  sc_attn);
    cudaGetSymbolAddress((void**)&g_samp,  sc_samp);
    cudaGetSymbolAddress((void**)&g_src2,  sc_src2);
    cudaGetSymbolAddress((void**)&g_src,   sc_src);
    cudaGetSymbolAddress((void**)&g_ffn,   sc_ffn);
    cudaGetSymbolAddress((void**)&g_ffn2,  sc_ffn2);

    // 1. q = cur_src + pos[:, -1]
    add_q_kernel<<<(ROWS_Q * D_MODEL / 4) / 256, 256>>>(cur_src, pos, g_q);

    // 2. value = (src_all + pos_flat) @ W_val + b_val   (M=131072, N=256, K=256)
    tgemm_kernel<true, false><<<dim3(D_MODEL / 128, ROWS_V / 128), 256>>>(
        src_all, pos, W_val, b_val, g_value, ROWS_V, D_MODEL, D_MODEL);

    // 3. off = q @ W_off + b_off                        (M=32768, N=256, K=256)
    tgemm_kernel<false, false><<<dim3(256 / 128, ROWS_Q / 128), 256>>>(
        g_q, nullptr, W_off, b_off, g_off, ROWS_Q, 256, D_MODEL);

    // 4. attn_logits = q @ W_attn + b_attn              (M=32768, N=128, K=256)
    tgemm_kernel<false, false><<<dim3(128 / 128, ROWS_Q / 128), 256>>>(
        g_q, nullptr, W_attn, b_attn, g_attn, ROWS_Q, 128, D_MODEL);

    // 5. fused softmax + deformable bilinear sampling
    sample_kernel<<<(BATCH * LQ * N_HEADS) / 8, 256>>>(
        g_off, g_attn, refpts, g_value, g_samp);

    // 6. src2 = samp @ W_out + b_out                    (M=32768, N=256, K=256)
    tgemm_kernel<false, false><<<dim3(D_MODEL / 128, ROWS_Q / 128), 256>>>(
        g_samp, nullptr, W_out, b_out, g_src2, ROWS_Q, D_MODEL, D_MODEL);

    // 7. src = LN(cur_src + src2)
    add_ln_kernel<<<ROWS_Q, 256>>>(cur_src, g_src2, gamma1, beta1, g_src);

    // 8. ffn_h = relu(src @ W1 + b1)                    (M=32768, N=1024, K=256)
    tgemm_kernel<false, true><<<dim3(D_FFN / 128, ROWS_Q / 128), 256>>>(
        g_src, nullptr, W1, b1, g_ffn, ROWS_Q, D_FFN, D_MODEL);

    // 9. ffn2 = ffn_h @ W2 + b2                         (M=32768, N=256, K=1024)
    tgemm_kernel<false, false><<<dim3(D_MODEL / 128, ROWS_Q / 128), 256>>>(
        g_ffn, nullptr, W2, b2, g_ffn2, ROWS_Q, D_MODEL, D_FFN);

    // 10. out = LN(src + ffn2)
    add_ln_kernel<<<ROWS_Q, 256>>>(g_src, g_ffn2, gamma2, beta2, out);
}

// round 4
// speedup vs baseline: 2.0383x; 1.0446x over previous
#include <cuda_runtime.h>
#include <cuda_bf16.h>
#include <cstdint>

// ---------------- problem constants ----------------
#define D_MODEL   256
#define N_HEADS   8
#define HEAD_DIM  32
#define N_LEVELS  4
#define N_POINTS  4
#define D_FFN     1024
#define HW        128
#define LQ        (HW * HW)            // 16384
#define LIN       (N_LEVELS * LQ)      // 65536
#define BATCH     2
#define ROWS_Q    (BATCH * LQ)         // 32768
#define ROWS_V    (BATCH * LIN)        // 131072

// ---------------- scratch (device globals; allocation-free rule) ----------
__device__ __align__(256) float sc_inp  [ROWS_V * D_MODEL];   // 134 MB
__device__ __align__(256) __nv_bfloat16 sc_value[ROWS_V * D_MODEL]; // 67 MB
__device__ __align__(256) float sc_q    [ROWS_Q * D_MODEL];   // 33.5 MB
__device__ __align__(256) float sc_off  [ROWS_Q * D_MODEL];   // 33.5 MB
__device__ __align__(256) float sc_attn [ROWS_Q * 128];       // 16.8 MB
__device__ __align__(256) float sc_samp [ROWS_Q * D_MODEL];   // 33.5 MB
__device__ __align__(256) float sc_src2 [ROWS_Q * D_MODEL];   // 33.5 MB
__device__ __align__(256) float sc_src  [ROWS_Q * D_MODEL];   // 33.5 MB
__device__ __align__(256) float sc_ffn  [ROWS_Q * D_FFN];     // 134 MB
__device__ __align__(256) float sc_ffn2 [ROWS_Q * D_MODEL];   // 33.5 MB

// ---------------- helpers --------------------------------------------------
__device__ __forceinline__ uint32_t f2tf32(float f) {
    uint32_t u;
    asm("cvt.rna.tf32.f32 %0, %1;" : "=r"(u) : "f"(f));
    return u;
}

__device__ __forceinline__ void mma_tf32(float c[4], const uint32_t a[4],
                                         const uint32_t b[2]) {
    asm volatile(
        "mma.sync.aligned.m16n8k8.row.col.f32.tf32.tf32.f32 "
        "{%0,%1,%2,%3}, {%4,%5,%6,%7}, {%8,%9}, {%0,%1,%2,%3};"
        : "+f"(c[0]), "+f"(c[1]), "+f"(c[2]), "+f"(c[3])
        : "r"(a[0]), "r"(a[1]), "r"(a[2]), "r"(a[3]), "r"(b[0]), "r"(b[1]));
}

__device__ __forceinline__ void cp_async16(void* smem, const void* gmem) {
    const uint32_t s = (uint32_t)__cvta_generic_to_shared(smem);
    asm volatile("cp.async.ca.shared.global [%0], [%1], 16;\n" :: "r"(s), "l"(gmem));
}
__device__ __forceinline__ void cp_commit() {
    asm volatile("cp.async.commit_group;\n");
}
template <int N>
__device__ __forceinline__ void cp_wait() {
    asm volatile("cp.async.wait_group %0;\n" :: "n"(N));
}

// ---------------- TF32 tensor-core GEMM, cp.async 3-stage -----------------
// C = A @ B + bias [, relu].  A: MxK rm, B: KxN rm, C: MxN rm.
// BM=BN=128, BK=16, 256 threads (8 warps, 2x4), warp tile 64x32.
// Requires M%128==0, N%128==0, K%16==0.
#define BK      16
#define A_PAD   20
#define B_PAD   136
#define STAGES  3

template <bool RELU, bool BF16_OUT>
__global__ __launch_bounds__(256)
void tgemm_kernel(const float* __restrict__ A, const float* __restrict__ B,
                  const float* __restrict__ bias, float* __restrict__ C,
                  __nv_bfloat16* __restrict__ Cb, int M, int N, int K)
{
    __shared__ float As[STAGES][128 * A_PAD];   // [m][k]
    __shared__ float Bs[STAGES][BK * B_PAD];    // [k][n]

    const int tid  = threadIdx.x;
    const int wid  = tid >> 5;
    const int lane = tid & 31;
    const int g    = lane >> 2;
    const int t    = lane & 3;

    const int bm = blockIdx.y * 128;
    const int bn = blockIdx.x * 128;
    const int wm = (wid & 1) * 64;
    const int wn = (wid >> 1) * 32;

    // global-load mapping
    const int la_m = tid >> 1;            // 0..127
    const int la_k = (tid & 1) * 8;       // 0 or 8
    const int lb_k = tid >> 4;            // 0..15
    const int lb_n = (tid & 15) * 8;      // 0..120

    const float* a_ptr = A + (size_t)(bm + la_m) * K + la_k;
    const float* b_ptr = B + (size_t)lb_k * N + bn + lb_n;

    const int nk = K / BK;

    auto load_tile = [&](int s, int k0) {
        float* as = &As[s][la_m * A_PAD + la_k];
        cp_async16(as,     a_ptr + k0);
        cp_async16(as + 4, a_ptr + k0 + 4);
        float* bs = &Bs[s][lb_k * B_PAD + lb_n];
        cp_async16(bs,     b_ptr + (size_t)k0 * N);
        cp_async16(bs + 4, b_ptr + (size_t)k0 * N + 4);
    };

    float acc[4][4][4] = {};  // [mt][nt][reg]

    // prologue: stages 0,1   (nk >= 2 always here)
    load_tile(0, 0);            cp_commit();
    load_tile(1, BK);           cp_commit();

    for (int i = 0; i < nk; ++i) {
        cp_wait<STAGES - 2>();      // tile i resident
        __syncthreads();

        const int nxt = i + STAGES - 1;
        if (nxt < nk) load_tile(nxt % STAGES, nxt * BK);
        cp_commit();

        const int s = i % STAGES;
        #pragma unroll
        for (int ks = 0; ks < BK; ks += 8) {
            uint32_t af[4][4];
            #pragma unroll
            for (int mt = 0; mt < 4; ++mt) {
                const float* p = &As[s][(wm + mt * 16 + g) * A_PAD + ks + t];
                af[mt][0] = f2tf32(p[0]);
                af[mt][1] = f2tf32(p[8 * A_PAD]);
                af[mt][2] = f2tf32(p[4]);
                af[mt][3] = f2tf32(p[8 * A_PAD + 4]);
            }
            uint32_t bf[4][2];
            #pragma unroll
            for (int nt = 0; nt < 4; ++nt) {
                const float* p = &Bs[s][(ks + t) * B_PAD + wn + nt * 8 + g];
                bf[nt][0] = f2tf32(p[0]);
                bf[nt][1] = f2tf32(p[4 * B_PAD]);
            }
            #pragma unroll
            for (int mt = 0; mt < 4; ++mt)
                #pragma unroll
                for (int nt = 0; nt < 4; ++nt)
                    mma_tf32(acc[mt][nt], af[mt], bf[nt]);
        }
        __syncthreads();
    }

    // ---- epilogue ----
    #pragma unroll
    for (int nt = 0; nt < 4; ++nt) {
        const int n = bn + wn + nt * 8 + t * 2;
        const float bx = bias[n], by = bias[n + 1];
        #pragma unroll
        for (int mt = 0; mt < 4; ++mt) {
            const int m = bm + wm + mt * 16 + g;
            float2 v0 = { acc[mt][nt][0] + bx, acc[mt][nt][1] + by };
            float2 v1 = { acc[mt][nt][2] + bx, acc[mt][nt][3] + by };
            if (RELU) {
                v0.x = fmaxf(v0.x, 0.f); v0.y = fmaxf(v0.y, 0.f);
                v1.x = fmaxf(v1.x, 0.f); v1.y = fmaxf(v1.y, 0.f);
            }
            if (BF16_OUT) {
                *(__nv_bfloat162*)&Cb[(size_t)m * N + n] =
                    __nv_bfloat162(__float2bfloat16_rn(v0.x), __float2bfloat16_rn(v0.y));
                *(__nv_bfloat162*)&Cb[(size_t)(m + 8) * N + n] =
                    __nv_bfloat162(__float2bfloat16_rn(v1.x), __float2bfloat16_rn(v1.y));
            } else {
                *(float2*)&C[(size_t)m * N + n]       = v0;
                *(float2*)&C[(size_t)(m + 8) * N + n] = v1;
            }
        }
    }
}

// ---------------- inp = src_all + pos (flat) -------------------------------
__global__ __launch_bounds__(256)
void add_inp_kernel(const float* __restrict__ a, const float* __restrict__ b,
                    float* __restrict__ o)
{
    const size_t i = (size_t)blockIdx.x * blockDim.x + threadIdx.x;
    float4 x = ((const float4*)a)[i];
    const float4 y = ((const float4*)b)[i];
    x.x += y.x; x.y += y.y; x.z += y.z; x.w += y.w;
    ((float4*)o)[i] = x;
}

// ---------------- q = cur_src + pos[:, -1] --------------------------------
__global__ __launch_bounds__(256)
void add_q_kernel(const float* __restrict__ cur, const float* __restrict__ pos,
                  float* __restrict__ q)
{
    const size_t i = (size_t)blockIdx.x * blockDim.x + threadIdx.x;
    const size_t per_batch = (size_t)LQ * D_MODEL / 4;
    const size_t n = i / per_batch;
    const size_t r = i - n * per_batch;
    float4 a = ((const float4*)cur)[i];
    const float4 b = ((const float4*)pos)[n * 4 * per_batch + 3 * per_batch + r];
    a.x += b.x; a.y += b.y; a.z += b.z; a.w += b.w;
    ((float4*)q)[i] = a;
}

// ---------------- fused softmax + deformable bilinear sampling ------------
// One warp per (n, q, h); lane = head-dim channel; value is bf16 (L2-resident).
__global__ __launch_bounds__(256)
void sample_kernel(const float* __restrict__ off, const float* __restrict__ attn,
                   const float* __restrict__ ref,
                   const __nv_bfloat16* __restrict__ value,
                   float* __restrict__ out)
{
    const int gw   = blockIdx.x * 8 + (threadIdx.x >> 5);
    const int lane = threadIdx.x & 31;
    const int h = gw & 7;
    const int q = (gw >> 3) & (LQ - 1);
    const int n = gw >> 17;

    const size_t row = (size_t)n * LQ + q;
    const float* ap = attn + row * 128 + h * 16;

    float logits[16];
    float mx = -1e30f;
    #pragma unroll
    for (int i = 0; i < 16; ++i) { logits[i] = ap[i]; mx = fmaxf(mx, logits[i]); }
    float ssum = 0.f;
    #pragma unroll
    for (int i = 0; i < 16; ++i) { logits[i] = __expf(logits[i] - mx); ssum += logits[i]; }
    const float inv = 1.f / ssum;

    const float* op = off + row * 256 + h * 32;
    const float* rp = ref + row * 8;
    const __nv_bfloat16* vb = value + (size_t)n * LIN * 256 + h * 32 + lane;

    float acc = 0.f;
    #pragma unroll
    for (int l = 0; l < N_LEVELS; ++l) {
        const float rx = rp[l * 2 + 0];
        const float ry = rp[l * 2 + 1];
        const int start = l * LQ;
        #pragma unroll
        for (int p = 0; p < N_POINTS; ++p) {
            const float x = fmaf(rx, 128.f, op[l * 8 + p * 2 + 0] - 0.5f);
            const float y = fmaf(ry, 128.f, op[l * 8 + p * 2 + 1] - 0.5f);
            const float x0f = floorf(x), y0f = floorf(y);
            const float wx = x - x0f, wy = y - y0f;
            const int x0 = (int)x0f, y0 = (int)y0f;
            const float aw = logits[l * 4 + p] * inv;

            const bool vx0 = (x0 >= 0) & (x0 < HW);
            const bool vx1 = (x0 + 1 >= 0) & (x0 + 1 < HW);
            const bool vy0 = (y0 >= 0) & (y0 < HW);
            const bool vy1 = (y0 + 1 >= 0) & (y0 + 1 < HW);

            if (vy0) {
                const size_t base = (size_t)(start + y0 * HW) * 256;
                if (vx0) acc = fmaf(__bfloat162float(vb[base + (size_t)x0 * 256]),
                                    (1.f - wx) * (1.f - wy) * aw, acc);
                if (vx1) acc = fmaf(__bfloat162float(vb[base + (size_t)(x0 + 1) * 256]),
                                    wx * (1.f - wy) * aw, acc);
            }
            if (vy1) {
                const size_t base = (size_t)(start + (y0 + 1) * HW) * 256;
                if (vx0) acc = fmaf(__bfloat162float(vb[base + (size_t)x0 * 256]),
                                    (1.f - wx) * wy * aw, acc);
                if (vx1) acc = fmaf(__bfloat162float(vb[base + (size_t)(x0 + 1) * 256]),
                                    wx * wy * aw, acc);
            }
        }
    }
    out[row * 256 + h * 32 + lane] = acc;
}

// ---------------- residual add + layernorm --------------------------------
__global__ __launch_bounds__(256)
void add_ln_kernel(const float* __restrict__ a, const float* __restrict__ b,
                   const float* __restrict__ gamma, const float* __restrict__ beta,
                   float* __restrict__ out)
{
    const int row = blockIdx.x;
    const int t = threadIdx.x;
    const size_t idx = (size_t)row * 256 + t;
    const float v = a[idx] + b[idx];

    __shared__ float red[8];
    float s = v;
    #pragma unroll
    for (int o = 16; o; o >>= 1) s += __shfl_xor_sync(0xffffffffu, s, o);
    if ((t & 31) == 0) red[t >> 5] = s;
    __syncthreads();
    float mean = 0.f;
    #pragma unroll
    for (int i = 0; i < 8; ++i) mean += red[i];
    mean *= (1.f / 256.f);
    __syncthreads();

    const float d = v - mean;
    float s2 = d * d;
    #pragma unroll
    for (int o = 16; o; o >>= 1) s2 += __shfl_xor_sync(0xffffffffu, s2, o);
    if ((t & 31) == 0) red[t >> 5] = s2;
    __syncthreads();
    float var = 0.f;
    #pragma unroll
    for (int i = 0; i < 8; ++i) var += red[i];
    var *= (1.f / 256.f);

    out[idx] = d * rsqrtf(var + 1e-5f) * gamma[t] + beta[t];
}

// ---------------- launch ---------------------------------------------------
extern "C" void kernel_launch(void* const* d_in, const int* in_sizes, int n_in,
                              void* d_out, int out_size)
{
    (void)in_sizes; (void)n_in; (void)out_size;
    const float* cur_src = (const float*)d_in[0];
    const float* src_all = (const float*)d_in[1];
    const float* pos     = (const float*)d_in[2];
    const float* refpts  = (const float*)d_in[3];
    const float* W_off   = (const float*)d_in[6];
    const float* b_off   = (const float*)d_in[7];
    const float* W_attn  = (const float*)d_in[8];
    const float* b_attn  = (const float*)d_in[9];
    const float* W_val   = (const float*)d_in[10];
    const float* b_val   = (const float*)d_in[11];
    const float* W_out   = (const float*)d_in[12];
    const float* b_out   = (const float*)d_in[13];
    const float* gamma1  = (const float*)d_in[14];
    const float* beta1   = (const float*)d_in[15];
    const float* W1      = (const float*)d_in[16];
    const float* b1      = (const float*)d_in[17];
    const float* W2      = (const float*)d_in[18];
    const float* b2      = (const float*)d_in[19];
    const float* gamma2  = (const float*)d_in[20];
    const float* beta2   = (const float*)d_in[21];
    float* out = (float*)d_out;

    float *g_inp, *g_q, *g_off, *g_attn, *g_samp, *g_src2, *g_src, *g_ffn, *g_ffn2;
    __nv_bfloat16* g_value;
    cudaGetSymbolAddress((void**)&g_inp,   sc_inp);
    cudaGetSymbolAddress((void**)&g_value, sc_value);
    cudaGetSymbolAddress((void**)&g_q,     sc_q);
    cudaGetSymbolAddress((void**)&g_off,   sc_off);
    cudaGetSymbolAddress((void**)&g_attn,  sc_attn);
    cudaGetSymbolAddress((void**)&g_samp,  sc_samp);
    cudaGetSymbolAddress((void**)&g_src2,  sc_src2);
    cudaGetSymbolAddress((void**)&g_src,   sc_src);
    cudaGetSymbolAddress((void**)&g_ffn,   sc_ffn);
    cudaGetSymbolAddress((void**)&g_ffn2,  sc_ffn2);

    // 0. inp = src_all + pos (flat layouts coincide)
    add_inp_kernel<<<(size_t)ROWS_V * D_MODEL / 4 / 256, 256>>>(src_all, pos, g_inp);

    // 1. q = cur_src + pos[:, -1]
    add_q_kernel<<<(ROWS_Q * D_MODEL / 4) / 256, 256>>>(cur_src, pos, g_q);

    // 2. value = inp @ W_val + b_val  -> bf16            (M=131072, N=256, K=256)
    tgemm_kernel<false, true><<<dim3(2, ROWS_V / 128), 256>>>(
        g_inp, W_val, b_val, nullptr, g_value, ROWS_V, D_MODEL, D_MODEL);

    // 3. off = q @ W_off + b_off                         (M=32768, N=256, K=256)
    tgemm_kernel<false, false><<<dim3(2, ROWS_Q / 128), 256>>>(
        g_q, W_off, b_off, g_off, nullptr, ROWS_Q, 256, D_MODEL);

    // 4. attn_logits = q @ W_attn + b_attn               (M=32768, N=128, K=256)
    tgemm_kernel<false, false><<<dim3(1, ROWS_Q / 128), 256>>>(
        g_q, W_attn, b_attn, g_attn, nullptr, ROWS_Q, 128, D_MODEL);

    // 5. fused softmax + deformable bilinear sampling
    sample_kernel<<<(BATCH * LQ * N_HEADS) / 8, 256>>>(
        g_off, g_attn, refpts, g_value, g_samp);

    // 6. src2 = samp @ W_out + b_out                     (M=32768, N=256, K=256)
    tgemm_kernel<false, false><<<dim3(2, ROWS_Q / 128), 256>>>(
        g_samp, W_out, b_out, g_src2, nullptr, ROWS_Q, D_MODEL, D_MODEL);

    // 7. src = LN(cur_src + src2)
    add_ln_kernel<<<ROWS_Q, 256>>>(cur_src, g_src2, gamma1, beta1, g_src);

    // 8. ffn_h = relu(src @ W1 + b1)                     (M=32768, N=1024, K=256)
    tgemm_kernel<true, false><<<dim3(D_FFN / 128, ROWS_Q / 128), 256>>>(
        g_src, W1, b1, g_ffn, nullptr, ROWS_Q, D_FFN, D_MODEL);

    // 9. ffn2 = ffn_h @ W2 + b2                          (M=32768, N=256, K=1024)
    tgemm_kernel<false, false><<<dim3(2, ROWS_Q / 128), 256>>>(
        g_ffn, W2, b2, g_ffn2, nullptr, ROWS_Q, D_MODEL, D_FFN);

    // 10. out = LN(src + ffn2)
    add_ln_kernel<<<ROWS_Q, 256>>>(g_src, g_ffn2, gamma2, beta2, out);
}